// round 14
// baseline (speedup 1.0000x reference)
#include <cuda_runtime.h>
#include <cuda_bf16.h>
#include <cstdint>

// ---------------------------------------------------------------------------
#define BATCH   8
#define DIM     256
#define HEADS   8
#define CH      32
#define HW      4096
#define QKV_C   768
#define HIDDEN  307
#define HID_PAD 320
#define M1_PAD  384

typedef __nv_bfloat16 bf16;

// ---------------------------------------------------------------------------
// Scratch (static device globals)
// ---------------------------------------------------------------------------
__device__ bf16  g_wqkvh[QKV_C * DIM],  g_wqkvl[QKV_C * DIM];
__device__ bf16  g_wprjh[DIM * DIM],    g_wprjl[DIM * DIM];
__device__ bf16  g_w1h  [M1_PAD * DIM], g_w1l  [M1_PAD * DIM];
__device__ bf16  g_w2h  [DIM * HID_PAD],g_w2l  [DIM * HID_PAD];
__device__ float g_b1p  [M1_PAD];
__device__ float g_qkv  [(size_t)BATCH * QKV_C * HW];
__device__ float g_qkvdw[(size_t)BATCH * QKV_C * HW];
__device__ float g_ssq  [BATCH * 2 * DIM];
__device__ float g_part [BATCH * HEADS * 8 * CH * CH];
__device__ float g_attn [BATCH * HEADS * CH * CH];
__device__ bf16  g_aoh  [(size_t)BATCH * DIM * HW];
__device__ bf16  g_aol  [(size_t)BATCH * DIM * HW];
__device__ bf16  g_outh [(size_t)BATCH * DIM * HW];
__device__ bf16  g_outl [(size_t)BATCH * DIM * HW];
__device__ bf16  g_hidh [(size_t)BATCH * M1_PAD * HW];
__device__ bf16  g_hidl [(size_t)BATCH * M1_PAD * HW];

// ---------------------------------------------------------------------------
__device__ __forceinline__ float gelu_tanh(float x) {
    float x3 = x * x * x;
    return 0.5f * x * (1.0f + tanhf(0.7978845608028654f * (x + 0.044715f * x3)));
}
__device__ __forceinline__ void split2(float v, bf16& h, bf16& l) {
    h = __float2bfloat16(v);
    l = __float2bfloat16(v - __bfloat162float(h));
}
__device__ __forceinline__ uint32_t packbf(bf16 a, bf16 b) {
    return ((uint32_t)__bfloat16_as_ushort(b) << 16) | (uint32_t)__bfloat16_as_ushort(a);
}
__device__ __forceinline__ void split_pack8(const float* f, uint32_t* hp, uint32_t* lp) {
#pragma unroll
    for (int q = 0; q < 4; q++) {
        bf16 h0, l0, h1, l1;
        split2(f[2 * q], h0, l0);
        split2(f[2 * q + 1], h1, l1);
        hp[q] = packbf(h0, h1);
        lp[q] = packbf(l0, l1);
    }
}

// ---------------------------------------------------------------------------
// PTX wrappers
// ---------------------------------------------------------------------------
__device__ __forceinline__ void ldsm_x4(uint32_t& r0, uint32_t& r1, uint32_t& r2,
                                        uint32_t& r3, uint32_t addr) {
    asm volatile("ldmatrix.sync.aligned.m8n8.x4.shared.b16 {%0,%1,%2,%3}, [%4];"
                 : "=r"(r0), "=r"(r1), "=r"(r2), "=r"(r3) : "r"(addr));
}
__device__ __forceinline__ void ldsm_x4_t(uint32_t& r0, uint32_t& r1, uint32_t& r2,
                                          uint32_t& r3, uint32_t addr) {
    asm volatile("ldmatrix.sync.aligned.m8n8.x4.trans.shared.b16 {%0,%1,%2,%3}, [%4];"
                 : "=r"(r0), "=r"(r1), "=r"(r2), "=r"(r3) : "r"(addr));
}
__device__ __forceinline__ void mma16816(float* d, const uint32_t* a,
                                         uint32_t b0, uint32_t b1) {
    asm volatile(
        "mma.sync.aligned.m16n8k16.row.col.f32.bf16.bf16.f32 "
        "{%0,%1,%2,%3}, {%4,%5,%6,%7}, {%8,%9}, {%0,%1,%2,%3};"
        : "+f"(d[0]), "+f"(d[1]), "+f"(d[2]), "+f"(d[3])
        : "r"(a[0]), "r"(a[1]), "r"(a[2]), "r"(a[3]), "r"(b0), "r"(b1));
}

// ---------------------------------------------------------------------------
// prep (3 micro-kernels so the 4th launch = qkv hgemm, for ncu capture)
// ---------------------------------------------------------------------------
#define PN1 (QKV_C * DIM)
#define PN2 (DIM * DIM)
#define PN3 (M1_PAD * DIM)
#define PN4 (DIM * HID_PAD)
#define PN5 (M1_PAD)
__global__ void prep_a_kernel(const float* __restrict__ wqkv)
{
    int i = blockIdx.x * blockDim.x + threadIdx.x;
    if (i < PN1) split2(wqkv[i], g_wqkvh[i], g_wqkvl[i]);
}
__global__ void prep_b_kernel(const float* __restrict__ wprj, const float* __restrict__ w1)
{
    int i = blockIdx.x * blockDim.x + threadIdx.x;
    if (i < PN2) { split2(wprj[i], g_wprjh[i], g_wprjl[i]); return; }
    i -= PN2;
    if (i < PN3) {
        int r = i >> 8;
        float v = (r < HIDDEN) ? w1[i] : 0.f;
        split2(v, g_w1h[i], g_w1l[i]);
    }
}
__global__ void prep_c_kernel(const float* __restrict__ w2, const float* __restrict__ b1)
{
    int i = blockIdx.x * blockDim.x + threadIdx.x;
    if (i < PN4) {
        int r = i / HID_PAD, c = i - r * HID_PAD;
        float v = (c < HIDDEN) ? w2[r * HIDDEN + c] : 0.f;
        split2(v, g_w2h[i], g_w2l[i]); return;
    }
    i -= PN4;
    if (i < PN5) g_b1p[i] = (i < HIDDEN) ? b1[i] : 0.f;
}

// ---------------------------------------------------------------------------
// bf16x3 tensor-core GEMM: C[b] = A(MxK) @ B[b](KxN) + epilogue.
// TERM-MAJOR MMA ordering across j2-pairs: all hh (8 distinct accs), then all
// hl, then all lh -> same-accumulator RAW distance 8 (was 4).
//   EPI 0 (QKV):  Cf = acc
//   EPI 1 (PROJ): v = acc + Res; Cf = v; (Ch,Cl) = split(v)
//   EPI 2 (MLP1): v = gelu(acc + bias); (Ch,Cl) = split(v)
//   EPI 3 (MLP2): Cf = acc + bias + Res  (Res may alias Cf)
// ---------------------------------------------------------------------------
template <int EPI, bool SPLITB>
__global__ __launch_bounds__(256, 2)
void hgemm_kernel(const bf16* __restrict__ Ah, const bf16* __restrict__ Al,
                  const bf16* __restrict__ Bhg, const bf16* __restrict__ Blg,
                  const float* __restrict__ Bfg,
                  float* __restrict__ Cfg, bf16* __restrict__ Chg, bf16* __restrict__ Clg,
                  const float* __restrict__ bias, const float* __restrict__ Resg,
                  int M, int N, int K, int bStride, int mStrideC)
{
    const int batch = blockIdx.z;
    const size_t cOff = (size_t)batch * mStrideC * N;

    const int m0 = blockIdx.y * 128;
    const int n0 = blockIdx.x * 128;

    __shared__ __align__(16) bf16 sA[2][2][128][24];
    __shared__ __align__(16) bf16 sB[2][2][16][136];

    const int tid  = threadIdx.x;
    const int lane = tid & 31;
    const int warp = tid >> 5;
    const int wm = warp & 3;
    const int wn = warp >> 2;

    const uint32_t sA0 = (uint32_t)__cvta_generic_to_shared(&sA[0][0][0][0]);
    const uint32_t sB0 = (uint32_t)__cvta_generic_to_shared(&sB[0][0][0][0]);
    const uint32_t A_PL = 128 * 24 * 2, A_BUF = 2 * A_PL;
    const uint32_t B_PL = 16 * 136 * 2, B_BUF = 2 * B_PL;

    const uint32_t aAddr = sA0 + ((wm * 32 + (lane & 15)) * 24) * 2 + ((lane >> 4) * 16);
    const uint32_t bAddr = sB0 + ((lane & 15) * 136 + wn * 64 + (lane >> 4) * 8) * 2;

    const int am = tid >> 1, ahalf = tid & 1;
    const int bk = tid >> 4, bseg  = tid & 15;
    const bf16* gAh = Ah + (size_t)(m0 + am) * K + ahalf * 8;
    const bf16* gAl = Al + (size_t)(m0 + am) * K + ahalf * 8;
    const bf16* gBh; const bf16* gBl; const float* gBf;
    if (SPLITB) {
        gBf = Bfg + (size_t)batch * bStride + (size_t)bk * N + n0 + bseg * 8;
    } else {
        gBh = Bhg + (size_t)batch * bStride + (size_t)bk * N + n0 + bseg * 8;
        gBl = Blg + (size_t)batch * bStride + (size_t)bk * N + n0 + bseg * 8;
    }

    const int numKT = K >> 4;
    int4 rah, ral, rbh, rbl;
    float4 rf0, rf1;

    // preload chunk 0
    rah = *(const int4*)gAh;
    ral = *(const int4*)gAl;
    if (SPLITB) { rf0 = *(const float4*)gBf; rf1 = *((const float4*)gBf + 1); }
    else        { rbh = *(const int4*)gBh;   rbl = *(const int4*)gBl; }
    *(int4*)&sA[0][0][am][ahalf * 8] = rah;
    *(int4*)&sA[0][1][am][ahalf * 8] = ral;
    if (SPLITB) {
        float f[8] = {rf0.x, rf0.y, rf0.z, rf0.w, rf1.x, rf1.y, rf1.z, rf1.w};
        uint32_t hp[4], lp[4];
        split_pack8(f, hp, lp);
        *(int4*)&sB[0][0][bk][bseg * 8] = *(int4*)hp;
        *(int4*)&sB[0][1][bk][bseg * 8] = *(int4*)lp;
    } else {
        *(int4*)&sB[0][0][bk][bseg * 8] = rbh;
        *(int4*)&sB[0][1][bk][bseg * 8] = rbl;
    }
    __syncthreads();

    float acc[2][8][4];
#pragma unroll
    for (int i = 0; i < 2; i++)
#pragma unroll
        for (int j = 0; j < 8; j++)
#pragma unroll
            for (int q = 0; q < 4; q++) acc[i][j][q] = 0.f;

#pragma unroll 2
    for (int kt = 0; kt < numKT; ++kt) {
        const int buf = kt & 1;
        if (kt + 1 < numKT) {
            const int kb = (kt + 1) << 4;
            rah = *(const int4*)(gAh + kb);
            ral = *(const int4*)(gAl + kb);
            if (SPLITB) {
                rf0 = *(const float4*)(gBf + (size_t)kb * N);
                rf1 = *((const float4*)(gBf + (size_t)kb * N) + 1);
            } else {
                rbh = *(const int4*)(gBh + (size_t)kb * N);
                rbl = *(const int4*)(gBl + (size_t)kb * N);
            }
        }

        uint32_t ah[2][4], al[2][4];
        {
            const uint32_t ab = aAddr + buf * A_BUF;
            ldsm_x4(ah[0][0], ah[0][1], ah[0][2], ah[0][3], ab);
            ldsm_x4(ah[1][0], ah[1][1], ah[1][2], ah[1][3], ab + 16 * 24 * 2);
            ldsm_x4(al[0][0], al[0][1], al[0][2], al[0][3], ab + A_PL);
            ldsm_x4(al[1][0], al[1][1], al[1][2], al[1][3], ab + A_PL + 16 * 24 * 2);
        }
        const uint32_t bb = bAddr + buf * B_BUF;

        // process j2 in pairs; term-major within the pair (RAW distance 8)
#pragma unroll
        for (int jp = 0; jp < 2; jp++) {
            uint32_t bhe[4], bho[4], ble[4], blo[4];
            ldsm_x4_t(bhe[0], bhe[1], bhe[2], bhe[3], bb + (2 * jp) * 32);
            ldsm_x4_t(bho[0], bho[1], bho[2], bho[3], bb + (2 * jp + 1) * 32);
            ldsm_x4_t(ble[0], ble[1], ble[2], ble[3], bb + B_PL + (2 * jp) * 32);
            ldsm_x4_t(blo[0], blo[1], blo[2], blo[3], bb + B_PL + (2 * jp + 1) * 32);
            const int j0 = 4 * jp;
            // hh (8 distinct accumulators)
            mma16816(acc[0][j0 + 0], ah[0], bhe[0], bhe[1]);
            mma16816(acc[1][j0 + 0], ah[1], bhe[0], bhe[1]);
            mma16816(acc[0][j0 + 1], ah[0], bhe[2], bhe[3]);
            mma16816(acc[1][j0 + 1], ah[1], bhe[2], bhe[3]);
            mma16816(acc[0][j0 + 2], ah[0], bho[0], bho[1]);
            mma16816(acc[1][j0 + 2], ah[1], bho[0], bho[1]);
            mma16816(acc[0][j0 + 3], ah[0], bho[2], bho[3]);
            mma16816(acc[1][j0 + 3], ah[1], bho[2], bho[3]);
            // hl
            mma16816(acc[0][j0 + 0], ah[0], ble[0], ble[1]);
            mma16816(acc[1][j0 + 0], ah[1], ble[0], ble[1]);
            mma16816(acc[0][j0 + 1], ah[0], ble[2], ble[3]);
            mma16816(acc[1][j0 + 1], ah[1], ble[2], ble[3]);
            mma16816(acc[0][j0 + 2], ah[0], blo[0], blo[1]);
            mma16816(acc[1][j0 + 2], ah[1], blo[0], blo[1]);
            mma16816(acc[0][j0 + 3], ah[0], blo[2], blo[3]);
            mma16816(acc[1][j0 + 3], ah[1], blo[2], blo[3]);
            // lh
            mma16816(acc[0][j0 + 0], al[0], bhe[0], bhe[1]);
            mma16816(acc[1][j0 + 0], al[1], bhe[0], bhe[1]);
            mma16816(acc[0][j0 + 1], al[0], bhe[2], bhe[3]);
            mma16816(acc[1][j0 + 1], al[1], bhe[2], bhe[3]);
            mma16816(acc[0][j0 + 2], al[0], bho[0], bho[1]);
            mma16816(acc[1][j0 + 2], al[1], bho[0], bho[1]);
            mma16816(acc[0][j0 + 3], al[0], bho[2], bho[3]);
            mma16816(acc[1][j0 + 3], al[1], bho[2], bho[3]);
        }

        if (kt + 1 < numKT) {
            const int nb = buf ^ 1;
            *(int4*)&sA[nb][0][am][ahalf * 8] = rah;
            *(int4*)&sA[nb][1][am][ahalf * 8] = ral;
            if (SPLITB) {
                float f[8] = {rf0.x, rf0.y, rf0.z, rf0.w, rf1.x, rf1.y, rf1.z, rf1.w};
                uint32_t hp[4], lp[4];
                split_pack8(f, hp, lp);
                *(int4*)&sB[nb][0][bk][bseg * 8] = *(int4*)hp;
                *(int4*)&sB[nb][1][bk][bseg * 8] = *(int4*)lp;
            } else {
                *(int4*)&sB[nb][0][bk][bseg * 8] = rbh;
                *(int4*)&sB[nb][1][bk][bseg * 8] = rbl;
            }
        }
        __syncthreads();
    }

    // epilogue
    float* Cf = (EPI != 2) ? (Cfg + cOff) : nullptr;
    bf16*  Chp = (EPI == 1 || EPI == 2) ? (Chg + cOff) : nullptr;
    bf16*  Clp = (EPI == 1 || EPI == 2) ? (Clg + cOff) : nullptr;
    const float* R = (EPI == 1 || EPI == 3) ? (Resg + cOff) : nullptr;

    const int g = lane >> 2, t = lane & 3;
#pragma unroll
    for (int i = 0; i < 2; i++) {
#pragma unroll
        for (int half = 0; half < 2; half++) {
            const int r = m0 + wm * 32 + i * 16 + half * 8 + g;
            float bi = 0.f;
            if (EPI == 2 || EPI == 3) bi = bias[r];
#pragma unroll
            for (int j = 0; j < 8; j++) {
                const int c = n0 + wn * 64 + j * 8 + t * 2;
                float v0 = acc[i][j][half * 2 + 0];
                float v1 = acc[i][j][half * 2 + 1];
                const size_t idx = (size_t)r * N + c;
                if (EPI == 0) {
                    Cf[idx] = v0; Cf[idx + 1] = v1;
                } else if (EPI == 1) {
                    v0 += R[idx]; v1 += R[idx + 1];
                    Cf[idx] = v0; Cf[idx + 1] = v1;
                    bf16 h0, l0, h1, l1;
                    split2(v0, h0, l0); split2(v1, h1, l1);
                    *(uint32_t*)&Chp[idx] = packbf(h0, h1);
                    *(uint32_t*)&Clp[idx] = packbf(l0, l1);
                } else if (EPI == 2) {
                    v0 = gelu_tanh(v0 + bi); v1 = gelu_tanh(v1 + bi);
                    bf16 h0, l0, h1, l1;
                    split2(v0, h0, l0); split2(v1, h1, l1);
                    *(uint32_t*)&Chp[idx] = packbf(h0, h1);
                    *(uint32_t*)&Clp[idx] = packbf(l0, l1);
                } else {
                    v0 += bi + R[idx]; v1 += bi + R[idx + 1];
                    Cf[idx] = v0; Cf[idx + 1] = v1;
                }
            }
        }
    }
}

// ---------------------------------------------------------------------------
// Depthwise 3x3 conv, smem-tiled: one block per (b,ch) 64x64 plane.
// ---------------------------------------------------------------------------
__global__ __launch_bounds__(256)
void dwconv_kernel(const float* __restrict__ in, const float* __restrict__ w,
                   float* __restrict__ out, float* __restrict__ ssq)
{
    const int bc = blockIdx.x;
    const int b  = bc / QKV_C;
    const int ch = bc - b * QKV_C;
    const int tid = threadIdx.x;

    __shared__ float t[66][68];
    __shared__ float red[8];

    if (tid < 264) {
        if (tid < 68)       t[0][tid] = 0.f;
        else if (tid < 136) t[65][tid - 68] = 0.f;
        else if (tid < 200) t[tid - 136 + 1][0] = 0.f;
        else                t[tid - 200 + 1][65] = 0.f;
    }

    const float4* ip4 = (const float4*)(in + (size_t)bc * HW);
#pragma unroll
    for (int j = 0; j < 4; j++) {
        int idx = tid + j * 256;
        int h = idx >> 4, w4 = idx & 15;
        float4 v = ip4[idx];
        t[h + 1][w4 * 4 + 1] = v.x;
        t[h + 1][w4 * 4 + 2] = v.y;
        t[h + 1][w4 * 4 + 3] = v.z;
        t[h + 1][w4 * 4 + 4] = v.w;
    }

    const float* wp = w + ch * 9;
    float k0 = wp[0], k1 = wp[1], k2 = wp[2];
    float k3 = wp[3], k4 = wp[4], k5 = wp[5];
    float k6 = wp[6], k7 = wp[7], k8 = wp[8];
    __syncthreads();

    float4* op4 = (float4*)(out + (size_t)bc * HW);
    float ss = 0.f;

#pragma unroll
    for (int grp = 0; grp < 4; grp++) {
        const int n = grp * 1024 + tid * 4;
        const int h = n >> 6, w0 = n & 63;
        float s0 = 0.f, s1 = 0.f, s2 = 0.f, s3 = 0.f;
#pragma unroll
        for (int dh = 0; dh < 3; dh++) {
            const float* r = &t[h + dh][w0];
            float r0 = r[0], r1 = r[1], r2 = r[2], r3 = r[3], r4 = r[4], r5 = r[5];
            float ka = (dh == 0) ? k0 : (dh == 1) ? k3 : k6;
            float kb = (dh == 0) ? k1 : (dh == 1) ? k4 : k7;
            float kc = (dh == 0) ? k2 : (dh == 1) ? k5 : k8;
            s0 = fmaf(ka, r0, fmaf(kb, r1, fmaf(kc, r2, s0)));
            s1 = fmaf(ka, r1, fmaf(kb, r2, fmaf(kc, r3, s1)));
            s2 = fmaf(ka, r2, fmaf(kb, r3, fmaf(kc, r4, s2)));
            s3 = fmaf(ka, r3, fmaf(kb, r4, fmaf(kc, r5, s3)));
        }
        float4 o; o.x = s0; o.y = s1; o.z = s2; o.w = s3;
        op4[grp * 256 + tid] = o;
        ss += s0 * s0 + s1 * s1 + s2 * s2 + s3 * s3;
    }

    if (ch < 2 * DIM) {
#pragma unroll
        for (int o = 16; o; o >>= 1) ss += __shfl_down_sync(0xffffffffu, ss, o);
        if ((tid & 31) == 0) red[tid >> 5] = ss;
        __syncthreads();
        if (tid == 0) {
            float s = 0.f;
#pragma unroll
            for (int i = 0; i < 8; i++) s += red[i];
            ssq[b * 2 * DIM + ch] = s;
        }
    }
}

// ---------------------------------------------------------------------------
// Partial attention logits, skewed smem (conflict-free LDS.128), 8 splits.
// ---------------------------------------------------------------------------
#define QP 160
__global__ __launch_bounds__(256)
void attn_partial_kernel(const float* __restrict__ qkvdw, float* __restrict__ part)
{
    const int split = blockIdx.x;
    const int bh = blockIdx.y;
    const int b = bh >> 3, head = bh & 7;

    const float* qp = qkvdw + ((size_t)(b * QKV_C + head * CH)) * HW;
    const float* kp = qkvdw + ((size_t)(b * QKV_C + DIM + head * CH)) * HW;

    __shared__ __align__(16) float qs[32][QP];
    __shared__ __align__(16) float ks[32][QP];

    const int tid = threadIdx.x;
    const int slice = tid >> 6;
    const int t64 = tid & 63;
    const int c0 = (t64 & 7) * 4;
    const int d0 = (t64 >> 3) * 4;
    const int skq = (c0 >> 2) * 4;
    const int skk = (d0 >> 2) * 4;

    float acc[4][4];
#pragma unroll
    for (int i = 0; i < 4; i++)
#pragma unroll
        for (int q = 0; q < 4; q++) acc[i][q] = 0.f;

    for (int t = 0; t < 4; ++t) {
        const int n0 = split * 512 + t * 128;
        __syncthreads();
#pragma unroll
        for (int it = 0; it < 4; it++) {
            int idx = tid + it * 256;
            int row = idx >> 5, j4 = idx & 31;
            int sk = (row >> 2) * 4;
            *(float4*)&qs[row][j4 * 4 + sk] = *(const float4*)&qp[(size_t)row * HW + n0 + j4 * 4];
            *(float4*)&ks[row][j4 * 4 + sk] = *(const float4*)&kp[(size_t)row * HW + n0 + j4 * 4];
        }
        __syncthreads();
#pragma unroll
        for (int jj = 0; jj < 32; jj += 4) {
            const int j = slice * 32 + jj;
            float4 qv[4], kv[4];
#pragma unroll
            for (int i = 0; i < 4; i++) qv[i] = *(const float4*)&qs[c0 + i][j + skq];
#pragma unroll
            for (int q = 0; q < 4; q++) kv[q] = *(const float4*)&ks[d0 + q][j + skk];
#pragma unroll
            for (int i = 0; i < 4; i++)
#pragma unroll
                for (int q = 0; q < 4; q++) {
                    acc[i][q] = fmaf(qv[i].x, kv[q].x, acc[i][q]);
                    acc[i][q] = fmaf(qv[i].y, kv[q].y, acc[i][q]);
                    acc[i][q] = fmaf(qv[i].z, kv[q].z, acc[i][q]);
                    acc[i][q] = fmaf(qv[i].w, kv[q].w, acc[i][q]);
                }
        }
    }

    __syncthreads();
    float* red = &qs[0][0];
#pragma unroll
    for (int i = 0; i < 4; i++)
#pragma unroll
        for (int q = 0; q < 4; q++)
            red[(slice * 64 + t64) * 16 + i * 4 + q] = acc[i][q];
    __syncthreads();

    float* pp = part + ((size_t)(bh * 8 + split)) * (CH * CH);
#pragma unroll
    for (int qq = 0; qq < 4; qq++) {
        const int e = tid * 4 + qq;
        const int c = e >> 5, d = e & 31;
        const int t2 = (d >> 2) * 8 + (c >> 2);
        const int f = (c & 3) * 4 + (d & 3);
        pp[e] = red[(0 * 64 + t2) * 16 + f] + red[(1 * 64 + t2) * 16 + f]
              + red[(2 * 64 + t2) * 16 + f] + red[(3 * 64 + t2) * 16 + f];
    }
}

// ---------------------------------------------------------------------------
// Reduce partials, fold norms + temperature, softmax.
// ---------------------------------------------------------------------------
__global__ __launch_bounds__(256)
void attn_softmax_kernel(const float* __restrict__ part,
                         const float* __restrict__ ssq,
                         const float* __restrict__ temp,
                         float* __restrict__ attn)
{
    const int bh = blockIdx.x;
    const int b = bh >> 3, head = bh & 7;
    const int tid = threadIdx.x;

    __shared__ float S[32][33];
    __shared__ float fq[32], fk[32];

    if (tid < 64) {
        int isK = tid >> 5, c = tid & 31;
        int ch = isK ? (DIM + head * CH + c) : (head * CH + c);
        float s = ssq[b * 2 * DIM + ch];
        float f = 1.0f / fmaxf(sqrtf(s), 1e-12f);
        if (isK) fk[c] = f; else fq[c] = f;
    }
    __syncthreads();

    const float T = temp[head];
#pragma unroll
    for (int r = 0; r < 4; r++) {
        int e = tid + r * 256;
        int c = e >> 5, d = e & 31;
        float s = 0.f;
#pragma unroll
        for (int p = 0; p < 8; p++) s += part[((size_t)(bh * 8 + p)) * (CH * CH) + e];
        S[c][d] = s * fq[c] * fk[d] * T;
    }
    __syncthreads();

    if (tid < 32) {
        float m = -1e30f;
#pragma unroll
        for (int d = 0; d < 32; d++) m = fmaxf(m, S[tid][d]);
        float sum = 0.f;
        float e[32];
#pragma unroll
        for (int d = 0; d < 32; d++) { e[d] = expf(S[tid][d] - m); sum += e[d]; }
        float inv = 1.0f / sum;
        float* ap = attn + (size_t)bh * CH * CH + tid * CH;
#pragma unroll
        for (int d = 0; d < 32; d++) ap[d] = e[d] * inv;
    }
}

// ---------------------------------------------------------------------------
// Apply attention: out[c,n] = sum_d attn[c,d] * v[d,n]  -> bf16 hi/lo
// ---------------------------------------------------------------------------
__global__ __launch_bounds__(256)
void attn_apply_kernel(const float* __restrict__ qkvdw,
                       const float* __restrict__ attn,
                       bf16* __restrict__ outh, bf16* __restrict__ outl)
{
    const int bh = blockIdx.y;
    const int b = bh >> 3, head = bh & 7;

    __shared__ float a[32][32];
    for (int i = threadIdx.x; i < 1024; i += 256)
        a[i >> 5][i & 31] = attn[(size_t)bh * 1024 + i];
    __syncthreads();

    const float2* vp2 = (const float2*)(qkvdw + ((size_t)(b * QKV_C + 2 * DIM + head * CH)) * HW);
    const size_t obase = ((size_t)(b * DIM + head * CH)) * HW;
    const int n2 = blockIdx.x * 256 + threadIdx.x;

    float2 o[32];
#pragma unroll
    for (int c = 0; c < 32; c++) { o[c].x = 0.f; o[c].y = 0.f; }
#pragma unroll
    for (int d = 0; d < 32; d++) {
        float2 vv = vp2[(size_t)d * (HW / 2) + n2];
#pragma unroll
        for (int c = 0; c < 32; c++) {
            o[c].x = fmaf(a[c][d], vv.x, o[c].x);
            o[c].y = fmaf(a[c][d], vv.y, o[c].y);
        }
    }
#pragma unroll
    for (int c = 0; c < 32; c++) {
        bf16 h0, l0, h1, l1;
        split2(o[c].x, h0, l0);
        split2(o[c].y, h1, l1);
        const size_t idx = obase + (size_t)c * HW + n2 * 2;
        *(uint32_t*)&outh[idx] = packbf(h0, h1);
        *(uint32_t*)&outl[idx] = packbf(l0, l1);
    }
}

// ---------------------------------------------------------------------------
extern "C" void kernel_launch(void* const* d_in, const int* in_sizes, int n_in,
                              void* d_out, int out_size)
{
    const float* x      = (const float*)d_in[0];
    const float* w_qkv  = (const float*)d_in[1];
    const float* w_dw   = (const float*)d_in[2];
    const float* temp   = (const float*)d_in[3];
    const float* w_proj = (const float*)d_in[4];
    const float* w_mlp1 = (const float*)d_in[5];
    const float* b_mlp1 = (const float*)d_in[6];
    const float* w_mlp2 = (const float*)d_in[7];
    const float* b_mlp2 = (const float*)d_in[8];
    float* out = (float*)d_out;

    bf16 *wqkvh, *wqkvl, *wprjh, *wprjl, *w1h, *w1l, *w2h, *w2l;
    bf16 *aoh, *aol, *outh, *outl, *hidh, *hidl;
    float *b1p, *qkv, *qkvdw, *ssq, *part, *attn;
    cudaGetSymbolAddress((void**)&wqkvh, g_wqkvh);
    cudaGetSymbolAddress((void**)&wqkvl, g_wqkvl);
    cudaGetSymbolAddress((void**)&wprjh, g_wprjh);
    cudaGetSymbolAddress((void**)&wprjl, g_wprjl);
    cudaGetSymbolAddress((void**)&w1h,   g_w1h);
    cudaGetSymbolAddress((void**)&w1l,   g_w1l);
    cudaGetSymbolAddress((void**)&w2h,   g_w2h);
    cudaGetSymbolAddress((void**)&w2l,   g_w2l);
    cudaGetSymbolAddress((void**)&b1p,   g_b1p);
    cudaGetSymbolAddress((void**)&qkv,   g_qkv);
    cudaGetSymbolAddress((void**)&qkvdw, g_qkvdw);
    cudaGetSymbolAddress((void**)&ssq,   g_ssq);
    cudaGetSymbolAddress((void**)&part,  g_part);
    cudaGetSymbolAddress((void**)&attn,  g_attn);
    cudaGetSymbolAddress((void**)&aoh,   g_aoh);
    cudaGetSymbolAddress((void**)&aol,   g_aol);
    cudaGetSymbolAddress((void**)&outh,  g_outh);
    cudaGetSymbolAddress((void**)&outl,  g_outl);
    cudaGetSymbolAddress((void**)&hidh,  g_hidh);
    cudaGetSymbolAddress((void**)&hidl,  g_hidl);

    // 0) weight splits (3 micro-launches so launch #4 = qkv hgemm for ncu)
    prep_a_kernel<<<(PN1 + 255) / 256, 256>>>(w_qkv);
    prep_b_kernel<<<(PN2 + PN3 + 255) / 256, 256>>>(w_proj, w_mlp1);
    prep_c_kernel<<<(PN4 + PN5 + 255) / 256, 256>>>(w_mlp2, b_mlp1);

    // 1) qkv = w_qkv @ x  (x split in-register; n-fastest grid)
    hgemm_kernel<0, true><<<dim3(HW / 128, QKV_C / 128, BATCH), 256>>>(
        wqkvh, wqkvl, nullptr, nullptr, x, qkv, nullptr, nullptr, nullptr, nullptr,
        QKV_C, HW, DIM, DIM * HW, QKV_C);

    // 2) depthwise 3x3 (smem-tiled) + full-plane sumsq
    dwconv_kernel<<<dim3(BATCH * QKV_C), 256>>>(qkv, w_dw, qkvdw, ssq);

    // 3) partial logits (skewed, conflict-free, 8 splits)
    attn_partial_kernel<<<dim3(8, BATCH * HEADS), 256>>>(qkvdw, part);

    // 4) reduce + scale + softmax
    attn_softmax_kernel<<<dim3(BATCH * HEADS), 256>>>(part, ssq, temp, attn);

    // 5) apply attention -> bf16 hi/lo
    attn_apply_kernel<<<dim3(HW / 512, BATCH * HEADS), 256>>>(qkvdw, attn, aoh, aol);

    // 6) x1 = x + w_proj @ attnout -> d_out fp32 + hi/lo
    hgemm_kernel<1, false><<<dim3(HW / 128, DIM / 128, BATCH), 256>>>(
        wprjh, wprjl, aoh, aol, nullptr, out, outh, outl, nullptr, x,
        DIM, HW, DIM, DIM * HW, DIM);

    // 7) hidden = gelu(w1 @ x1 + b1) -> hi/lo
    hgemm_kernel<2, false><<<dim3(HW / 128, M1_PAD / 128, BATCH), 256>>>(
        w1h, w1l, outh, outl, nullptr, nullptr, hidh, hidl, b1p, nullptr,
        M1_PAD, HW, DIM, DIM * HW, M1_PAD);

    // 8) d_out = x1 + w2 @ hidden + b2  (in place)
    hgemm_kernel<3, false><<<dim3(HW / 128, DIM / 128, BATCH), 256>>>(
        w2h, w2l, hidh, hidl, nullptr, out, nullptr, nullptr, b_mlp2, out,
        DIM, HW, HID_PAD, M1_PAD * HW, DIM);
}

// round 15
// speedup vs baseline: 1.1711x; 1.1711x over previous
#include <cuda_runtime.h>
#include <cuda_bf16.h>
#include <cstdint>

// ---------------------------------------------------------------------------
#define BATCH   8
#define DIM     256
#define HEADS   8
#define CH      32
#define HW      4096
#define QKV_C   768
#define HIDDEN  307
#define HID_PAD 320
#define M1_PAD  384

typedef __nv_bfloat16 bf16;

// ---------------------------------------------------------------------------
// Scratch (static device globals). Weights: hi plane only (bf16x2 scheme).
// Activations keep hi/lo split (B operand stays ~fp32 accurate).
// ---------------------------------------------------------------------------
__device__ bf16  g_wqkvh[QKV_C * DIM];
__device__ bf16  g_wprjh[DIM * DIM];
__device__ bf16  g_w1h  [M1_PAD * DIM];
__device__ bf16  g_w2h  [DIM * HID_PAD];
__device__ float g_b1p  [M1_PAD];
__device__ float g_qkv  [(size_t)BATCH * QKV_C * HW];
__device__ float g_qkvdw[(size_t)BATCH * QKV_C * HW];
__device__ float g_ssq  [BATCH * 2 * DIM];
__device__ float g_part [BATCH * HEADS * 8 * CH * CH];
__device__ float g_attn [BATCH * HEADS * CH * CH];
__device__ bf16  g_aoh  [(size_t)BATCH * DIM * HW];
__device__ bf16  g_aol  [(size_t)BATCH * DIM * HW];
__device__ bf16  g_outh [(size_t)BATCH * DIM * HW];
__device__ bf16  g_outl [(size_t)BATCH * DIM * HW];
__device__ bf16  g_hidh [(size_t)BATCH * M1_PAD * HW];
__device__ bf16  g_hidl [(size_t)BATCH * M1_PAD * HW];

// ---------------------------------------------------------------------------
__device__ __forceinline__ float gelu_tanh(float x) {
    float x3 = x * x * x;
    return 0.5f * x * (1.0f + tanhf(0.7978845608028654f * (x + 0.044715f * x3)));
}
__device__ __forceinline__ void split2(float v, bf16& h, bf16& l) {
    h = __float2bfloat16(v);
    l = __float2bfloat16(v - __bfloat162float(h));
}
__device__ __forceinline__ uint32_t packbf(bf16 a, bf16 b) {
    return ((uint32_t)__bfloat16_as_ushort(b) << 16) | (uint32_t)__bfloat16_as_ushort(a);
}
__device__ __forceinline__ void split_pack8(const float* f, uint32_t* hp, uint32_t* lp) {
#pragma unroll
    for (int q = 0; q < 4; q++) {
        bf16 h0, l0, h1, l1;
        split2(f[2 * q], h0, l0);
        split2(f[2 * q + 1], h1, l1);
        hp[q] = packbf(h0, h1);
        lp[q] = packbf(l0, l1);
    }
}

// ---------------------------------------------------------------------------
// PTX wrappers
// ---------------------------------------------------------------------------
__device__ __forceinline__ void ldsm_x4(uint32_t& r0, uint32_t& r1, uint32_t& r2,
                                        uint32_t& r3, uint32_t addr) {
    asm volatile("ldmatrix.sync.aligned.m8n8.x4.shared.b16 {%0,%1,%2,%3}, [%4];"
                 : "=r"(r0), "=r"(r1), "=r"(r2), "=r"(r3) : "r"(addr));
}
__device__ __forceinline__ void ldsm_x4_t(uint32_t& r0, uint32_t& r1, uint32_t& r2,
                                          uint32_t& r3, uint32_t addr) {
    asm volatile("ldmatrix.sync.aligned.m8n8.x4.trans.shared.b16 {%0,%1,%2,%3}, [%4];"
                 : "=r"(r0), "=r"(r1), "=r"(r2), "=r"(r3) : "r"(addr));
}
__device__ __forceinline__ void mma16816(float* d, const uint32_t* a,
                                         uint32_t b0, uint32_t b1) {
    asm volatile(
        "mma.sync.aligned.m16n8k16.row.col.f32.bf16.bf16.f32 "
        "{%0,%1,%2,%3}, {%4,%5,%6,%7}, {%8,%9}, {%0,%1,%2,%3};"
        : "+f"(d[0]), "+f"(d[1]), "+f"(d[2]), "+f"(d[3])
        : "r"(a[0]), "r"(a[1]), "r"(a[2]), "r"(a[3]), "r"(b0), "r"(b1));
}

// ---------------------------------------------------------------------------
// prep (3 micro-kernels so the 4th launch = qkv hgemm, for ncu capture)
// ---------------------------------------------------------------------------
#define PN1 (QKV_C * DIM)
#define PN2 (DIM * DIM)
#define PN3 (M1_PAD * DIM)
#define PN4 (DIM * HID_PAD)
#define PN5 (M1_PAD)
__global__ void prep_a_kernel(const float* __restrict__ wqkv)
{
    int i = blockIdx.x * blockDim.x + threadIdx.x;
    if (i < PN1) g_wqkvh[i] = __float2bfloat16(wqkv[i]);
}
__global__ void prep_b_kernel(const float* __restrict__ wprj, const float* __restrict__ w1)
{
    int i = blockIdx.x * blockDim.x + threadIdx.x;
    if (i < PN2) { g_wprjh[i] = __float2bfloat16(wprj[i]); return; }
    i -= PN2;
    if (i < PN3) {
        int r = i >> 8;
        g_w1h[i] = __float2bfloat16((r < HIDDEN) ? w1[i] : 0.f);
    }
}
__global__ void prep_c_kernel(const float* __restrict__ w2, const float* __restrict__ b1)
{
    int i = blockIdx.x * blockDim.x + threadIdx.x;
    if (i < PN4) {
        int r = i / HID_PAD, c = i - r * HID_PAD;
        g_w2h[i] = __float2bfloat16((c < HIDDEN) ? w2[r * HIDDEN + c] : 0.f);
        return;
    }
    i -= PN4;
    if (i < PN5) g_b1p[i] = (i < HIDDEN) ? b1[i] : 0.f;
}

// ---------------------------------------------------------------------------
// bf16x2 tensor-core GEMM: C[b] = bf16(A)(MxK) @ (Bh+Bl)[b](KxN) + epilogue.
// A hi-plane only; two MMA terms per B pair (hh + hl), term-major across
// j2-pairs so same-accumulator RAW distance is 8.
//   EPI 0 (QKV):  Cf = acc
//   EPI 1 (PROJ): v = acc + Res; Cf = v; (Ch,Cl) = split(v)
//   EPI 2 (MLP1): v = gelu(acc + bias); (Ch,Cl) = split(v)
//   EPI 3 (MLP2): Cf = acc + bias + Res  (Res may alias Cf)
// ---------------------------------------------------------------------------
template <int EPI, bool SPLITB>
__global__ __launch_bounds__(256, 2)
void hgemm_kernel(const bf16* __restrict__ Ah,
                  const bf16* __restrict__ Bhg, const bf16* __restrict__ Blg,
                  const float* __restrict__ Bfg,
                  float* __restrict__ Cfg, bf16* __restrict__ Chg, bf16* __restrict__ Clg,
                  const float* __restrict__ bias, const float* __restrict__ Resg,
                  int M, int N, int K, int bStride, int mStrideC)
{
    const int batch = blockIdx.z;
    const size_t cOff = (size_t)batch * mStrideC * N;

    const int m0 = blockIdx.y * 128;
    const int n0 = blockIdx.x * 128;

    __shared__ __align__(16) bf16 sA[2][128][24];       // single hi plane
    __shared__ __align__(16) bf16 sB[2][2][16][136];

    const int tid  = threadIdx.x;
    const int lane = tid & 31;
    const int warp = tid >> 5;
    const int wm = warp & 3;
    const int wn = warp >> 2;

    const uint32_t sA0 = (uint32_t)__cvta_generic_to_shared(&sA[0][0][0]);
    const uint32_t sB0 = (uint32_t)__cvta_generic_to_shared(&sB[0][0][0][0]);
    const uint32_t A_BUF = 128 * 24 * 2;
    const uint32_t B_PL = 16 * 136 * 2, B_BUF = 2 * B_PL;

    const uint32_t aAddr = sA0 + ((wm * 32 + (lane & 15)) * 24) * 2 + ((lane >> 4) * 16);
    const uint32_t bAddr = sB0 + ((lane & 15) * 136 + wn * 64 + (lane >> 4) * 8) * 2;

    const int am = tid >> 1, ahalf = tid & 1;
    const int bk = tid >> 4, bseg  = tid & 15;
    const bf16* gAh = Ah + (size_t)(m0 + am) * K + ahalf * 8;
    const bf16* gBh; const bf16* gBl; const float* gBf;
    if (SPLITB) {
        gBf = Bfg + (size_t)batch * bStride + (size_t)bk * N + n0 + bseg * 8;
    } else {
        gBh = Bhg + (size_t)batch * bStride + (size_t)bk * N + n0 + bseg * 8;
        gBl = Blg + (size_t)batch * bStride + (size_t)bk * N + n0 + bseg * 8;
    }

    const int numKT = K >> 4;
    int4 rah, rbh, rbl;
    float4 rf0, rf1;

    // preload chunk 0
    rah = *(const int4*)gAh;
    if (SPLITB) { rf0 = *(const float4*)gBf; rf1 = *((const float4*)gBf + 1); }
    else        { rbh = *(const int4*)gBh;   rbl = *(const int4*)gBl; }
    *(int4*)&sA[0][am][ahalf * 8] = rah;
    if (SPLITB) {
        float f[8] = {rf0.x, rf0.y, rf0.z, rf0.w, rf1.x, rf1.y, rf1.z, rf1.w};
        uint32_t hp[4], lp[4];
        split_pack8(f, hp, lp);
        *(int4*)&sB[0][0][bk][bseg * 8] = *(int4*)hp;
        *(int4*)&sB[0][1][bk][bseg * 8] = *(int4*)lp;
    } else {
        *(int4*)&sB[0][0][bk][bseg * 8] = rbh;
        *(int4*)&sB[0][1][bk][bseg * 8] = rbl;
    }
    __syncthreads();

    float acc[2][8][4];
#pragma unroll
    for (int i = 0; i < 2; i++)
#pragma unroll
        for (int j = 0; j < 8; j++)
#pragma unroll
            for (int q = 0; q < 4; q++) acc[i][j][q] = 0.f;

#pragma unroll 2
    for (int kt = 0; kt < numKT; ++kt) {
        const int buf = kt & 1;
        if (kt + 1 < numKT) {
            const int kb = (kt + 1) << 4;
            rah = *(const int4*)(gAh + kb);
            if (SPLITB) {
                rf0 = *(const float4*)(gBf + (size_t)kb * N);
                rf1 = *((const float4*)(gBf + (size_t)kb * N) + 1);
            } else {
                rbh = *(const int4*)(gBh + (size_t)kb * N);
                rbl = *(const int4*)(gBl + (size_t)kb * N);
            }
        }

        uint32_t ah[2][4];
        {
            const uint32_t ab = aAddr + buf * A_BUF;
            ldsm_x4(ah[0][0], ah[0][1], ah[0][2], ah[0][3], ab);
            ldsm_x4(ah[1][0], ah[1][1], ah[1][2], ah[1][3], ab + 16 * 24 * 2);
        }
        const uint32_t bb = bAddr + buf * B_BUF;

        // j2-pairs; term-major (hh x8 then hl x8) -> RAW distance 8
#pragma unroll
        for (int jp = 0; jp < 2; jp++) {
            uint32_t bhe[4], bho[4], ble[4], blo[4];
            ldsm_x4_t(bhe[0], bhe[1], bhe[2], bhe[3], bb + (2 * jp) * 32);
            ldsm_x4_t(bho[0], bho[1], bho[2], bho[3], bb + (2 * jp + 1) * 32);
            ldsm_x4_t(ble[0], ble[1], ble[2], ble[3], bb + B_PL + (2 * jp) * 32);
            ldsm_x4_t(blo[0], blo[1], blo[2], blo[3], bb + B_PL + (2 * jp + 1) * 32);
            const int j0 = 4 * jp;
            // hh
            mma16816(acc[0][j0 + 0], ah[0], bhe[0], bhe[1]);
            mma16816(acc[1][j0 + 0], ah[1], bhe[0], bhe[1]);
            mma16816(acc[0][j0 + 1], ah[0], bhe[2], bhe[3]);
            mma16816(acc[1][j0 + 1], ah[1], bhe[2], bhe[3]);
            mma16816(acc[0][j0 + 2], ah[0], bho[0], bho[1]);
            mma16816(acc[1][j0 + 2], ah[1], bho[0], bho[1]);
            mma16816(acc[0][j0 + 3], ah[0], bho[2], bho[3]);
            mma16816(acc[1][j0 + 3], ah[1], bho[2], bho[3]);
            // hl
            mma16816(acc[0][j0 + 0], ah[0], ble[0], ble[1]);
            mma16816(acc[1][j0 + 0], ah[1], ble[0], ble[1]);
            mma16816(acc[0][j0 + 1], ah[0], ble[2], ble[3]);
            mma16816(acc[1][j0 + 1], ah[1], ble[2], ble[3]);
            mma16816(acc[0][j0 + 2], ah[0], blo[0], blo[1]);
            mma16816(acc[1][j0 + 2], ah[1], blo[0], blo[1]);
            mma16816(acc[0][j0 + 3], ah[0], blo[2], blo[3]);
            mma16816(acc[1][j0 + 3], ah[1], blo[2], blo[3]);
        }

        if (kt + 1 < numKT) {
            const int nb = buf ^ 1;
            *(int4*)&sA[nb][am][ahalf * 8] = rah;
            if (SPLITB) {
                float f[8] = {rf0.x, rf0.y, rf0.z, rf0.w, rf1.x, rf1.y, rf1.z, rf1.w};
                uint32_t hp[4], lp[4];
                split_pack8(f, hp, lp);
                *(int4*)&sB[nb][0][bk][bseg * 8] = *(int4*)hp;
                *(int4*)&sB[nb][1][bk][bseg * 8] = *(int4*)lp;
            } else {
                *(int4*)&sB[nb][0][bk][bseg * 8] = rbh;
                *(int4*)&sB[nb][1][bk][bseg * 8] = rbl;
            }
        }
        __syncthreads();
    }

    // epilogue
    float* Cf = (EPI != 2) ? (Cfg + cOff) : nullptr;
    bf16*  Chp = (EPI == 1 || EPI == 2) ? (Chg + cOff) : nullptr;
    bf16*  Clp = (EPI == 1 || EPI == 2) ? (Clg + cOff) : nullptr;
    const float* R = (EPI == 1 || EPI == 3) ? (Resg + cOff) : nullptr;

    const int g = lane >> 2, t = lane & 3;
#pragma unroll
    for (int i = 0; i < 2; i++) {
#pragma unroll
        for (int half = 0; half < 2; half++) {
            const int r = m0 + wm * 32 + i * 16 + half * 8 + g;
            float bi = 0.f;
            if (EPI == 2 || EPI == 3) bi = bias[r];
#pragma unroll
            for (int j = 0; j < 8; j++) {
                const int c = n0 + wn * 64 + j * 8 + t * 2;
                float v0 = acc[i][j][half * 2 + 0];
                float v1 = acc[i][j][half * 2 + 1];
                const size_t idx = (size_t)r * N + c;
                if (EPI == 0) {
                    Cf[idx] = v0; Cf[idx + 1] = v1;
                } else if (EPI == 1) {
                    v0 += R[idx]; v1 += R[idx + 1];
                    Cf[idx] = v0; Cf[idx + 1] = v1;
                    bf16 h0, l0, h1, l1;
                    split2(v0, h0, l0); split2(v1, h1, l1);
                    *(uint32_t*)&Chp[idx] = packbf(h0, h1);
                    *(uint32_t*)&Clp[idx] = packbf(l0, l1);
                } else if (EPI == 2) {
                    v0 = gelu_tanh(v0 + bi); v1 = gelu_tanh(v1 + bi);
                    bf16 h0, l0, h1, l1;
                    split2(v0, h0, l0); split2(v1, h1, l1);
                    *(uint32_t*)&Chp[idx] = packbf(h0, h1);
                    *(uint32_t*)&Clp[idx] = packbf(l0, l1);
                } else {
                    v0 += bi + R[idx]; v1 += bi + R[idx + 1];
                    Cf[idx] = v0; Cf[idx + 1] = v1;
                }
            }
        }
    }
}

// ---------------------------------------------------------------------------
// Depthwise 3x3 conv, smem-tiled: one block per (b,ch) 64x64 plane.
// ---------------------------------------------------------------------------
__global__ __launch_bounds__(256)
void dwconv_kernel(const float* __restrict__ in, const float* __restrict__ w,
                   float* __restrict__ out, float* __restrict__ ssq)
{
    const int bc = blockIdx.x;
    const int b  = bc / QKV_C;
    const int ch = bc - b * QKV_C;
    const int tid = threadIdx.x;

    __shared__ float t[66][68];
    __shared__ float red[8];

    if (tid < 264) {
        if (tid < 68)       t[0][tid] = 0.f;
        else if (tid < 136) t[65][tid - 68] = 0.f;
        else if (tid < 200) t[tid - 136 + 1][0] = 0.f;
        else                t[tid - 200 + 1][65] = 0.f;
    }

    const float4* ip4 = (const float4*)(in + (size_t)bc * HW);
#pragma unroll
    for (int j = 0; j < 4; j++) {
        int idx = tid + j * 256;
        int h = idx >> 4, w4 = idx & 15;
        float4 v = ip4[idx];
        t[h + 1][w4 * 4 + 1] = v.x;
        t[h + 1][w4 * 4 + 2] = v.y;
        t[h + 1][w4 * 4 + 3] = v.z;
        t[h + 1][w4 * 4 + 4] = v.w;
    }

    const float* wp = w + ch * 9;
    float k0 = wp[0], k1 = wp[1], k2 = wp[2];
    float k3 = wp[3], k4 = wp[4], k5 = wp[5];
    float k6 = wp[6], k7 = wp[7], k8 = wp[8];
    __syncthreads();

    float4* op4 = (float4*)(out + (size_t)bc * HW);
    float ss = 0.f;

#pragma unroll
    for (int grp = 0; grp < 4; grp++) {
        const int n = grp * 1024 + tid * 4;
        const int h = n >> 6, w0 = n & 63;
        float s0 = 0.f, s1 = 0.f, s2 = 0.f, s3 = 0.f;
#pragma unroll
        for (int dh = 0; dh < 3; dh++) {
            const float* r = &t[h + dh][w0];
            float r0 = r[0], r1 = r[1], r2 = r[2], r3 = r[3], r4 = r[4], r5 = r[5];
            float ka = (dh == 0) ? k0 : (dh == 1) ? k3 : k6;
            float kb = (dh == 0) ? k1 : (dh == 1) ? k4 : k7;
            float kc = (dh == 0) ? k2 : (dh == 1) ? k5 : k8;
            s0 = fmaf(ka, r0, fmaf(kb, r1, fmaf(kc, r2, s0)));
            s1 = fmaf(ka, r1, fmaf(kb, r2, fmaf(kc, r3, s1)));
            s2 = fmaf(ka, r2, fmaf(kb, r3, fmaf(kc, r4, s2)));
            s3 = fmaf(ka, r3, fmaf(kb, r4, fmaf(kc, r5, s3)));
        }
        float4 o; o.x = s0; o.y = s1; o.z = s2; o.w = s3;
        op4[grp * 256 + tid] = o;
        ss += s0 * s0 + s1 * s1 + s2 * s2 + s3 * s3;
    }

    if (ch < 2 * DIM) {
#pragma unroll
        for (int o = 16; o; o >>= 1) ss += __shfl_down_sync(0xffffffffu, ss, o);
        if ((tid & 31) == 0) red[tid >> 5] = ss;
        __syncthreads();
        if (tid == 0) {
            float s = 0.f;
#pragma unroll
            for (int i = 0; i < 8; i++) s += red[i];
            ssq[b * 2 * DIM + ch] = s;
        }
    }
}

// ---------------------------------------------------------------------------
// Partial attention logits, skewed smem (conflict-free LDS.128), 8 splits.
// ---------------------------------------------------------------------------
#define QP 160
__global__ __launch_bounds__(256)
void attn_partial_kernel(const float* __restrict__ qkvdw, float* __restrict__ part)
{
    const int split = blockIdx.x;
    const int bh = blockIdx.y;
    const int b = bh >> 3, head = bh & 7;

    const float* qp = qkvdw + ((size_t)(b * QKV_C + head * CH)) * HW;
    const float* kp = qkvdw + ((size_t)(b * QKV_C + DIM + head * CH)) * HW;

    __shared__ __align__(16) float qs[32][QP];
    __shared__ __align__(16) float ks[32][QP];

    const int tid = threadIdx.x;
    const int slice = tid >> 6;
    const int t64 = tid & 63;
    const int c0 = (t64 & 7) * 4;
    const int d0 = (t64 >> 3) * 4;
    const int skq = (c0 >> 2) * 4;
    const int skk = (d0 >> 2) * 4;

    float acc[4][4];
#pragma unroll
    for (int i = 0; i < 4; i++)
#pragma unroll
        for (int q = 0; q < 4; q++) acc[i][q] = 0.f;

    for (int t = 0; t < 4; ++t) {
        const int n0 = split * 512 + t * 128;
        __syncthreads();
#pragma unroll
        for (int it = 0; it < 4; it++) {
            int idx = tid + it * 256;
            int row = idx >> 5, j4 = idx & 31;
            int sk = (row >> 2) * 4;
            *(float4*)&qs[row][j4 * 4 + sk] = *(const float4*)&qp[(size_t)row * HW + n0 + j4 * 4];
            *(float4*)&ks[row][j4 * 4 + sk] = *(const float4*)&kp[(size_t)row * HW + n0 + j4 * 4];
        }
        __syncthreads();
#pragma unroll
        for (int jj = 0; jj < 32; jj += 4) {
            const int j = slice * 32 + jj;
            float4 qv[4], kv[4];
#pragma unroll
            for (int i = 0; i < 4; i++) qv[i] = *(const float4*)&qs[c0 + i][j + skq];
#pragma unroll
            for (int q = 0; q < 4; q++) kv[q] = *(const float4*)&ks[d0 + q][j + skk];
#pragma unroll
            for (int i = 0; i < 4; i++)
#pragma unroll
                for (int q = 0; q < 4; q++) {
                    acc[i][q] = fmaf(qv[i].x, kv[q].x, acc[i][q]);
                    acc[i][q] = fmaf(qv[i].y, kv[q].y, acc[i][q]);
                    acc[i][q] = fmaf(qv[i].z, kv[q].z, acc[i][q]);
                    acc[i][q] = fmaf(qv[i].w, kv[q].w, acc[i][q]);
                }
        }
    }

    __syncthreads();
    float* red = &qs[0][0];
#pragma unroll
    for (int i = 0; i < 4; i++)
#pragma unroll
        for (int q = 0; q < 4; q++)
            red[(slice * 64 + t64) * 16 + i * 4 + q] = acc[i][q];
    __syncthreads();

    float* pp = part + ((size_t)(bh * 8 + split)) * (CH * CH);
#pragma unroll
    for (int qq = 0; qq < 4; qq++) {
        const int e = tid * 4 + qq;
        const int c = e >> 5, d = e & 31;
        const int t2 = (d >> 2) * 8 + (c >> 2);
        const int f = (c & 3) * 4 + (d & 3);
        pp[e] = red[(0 * 64 + t2) * 16 + f] + red[(1 * 64 + t2) * 16 + f]
              + red[(2 * 64 + t2) * 16 + f] + red[(3 * 64 + t2) * 16 + f];
    }
}

// ---------------------------------------------------------------------------
// Reduce partials, fold norms + temperature, softmax.
// ---------------------------------------------------------------------------
__global__ __launch_bounds__(256)
void attn_softmax_kernel(const float* __restrict__ part,
                         const float* __restrict__ ssq,
                         const float* __restrict__ temp,
                         float* __restrict__ attn)
{
    const int bh = blockIdx.x;
    const int b = bh >> 3, head = bh & 7;
    const int tid = threadIdx.x;

    __shared__ float S[32][33];
    __shared__ float fq[32], fk[32];

    if (tid < 64) {
        int isK = tid >> 5, c = tid & 31;
        int ch = isK ? (DIM + head * CH + c) : (head * CH + c);
        float s = ssq[b * 2 * DIM + ch];
        float f = 1.0f / fmaxf(sqrtf(s), 1e-12f);
        if (isK) fk[c] = f; else fq[c] = f;
    }
    __syncthreads();

    const float T = temp[head];
#pragma unroll
    for (int r = 0; r < 4; r++) {
        int e = tid + r * 256;
        int c = e >> 5, d = e & 31;
        float s = 0.f;
#pragma unroll
        for (int p = 0; p < 8; p++) s += part[((size_t)(bh * 8 + p)) * (CH * CH) + e];
        S[c][d] = s * fq[c] * fk[d] * T;
    }
    __syncthreads();

    if (tid < 32) {
        float m = -1e30f;
#pragma unroll
        for (int d = 0; d < 32; d++) m = fmaxf(m, S[tid][d]);
        float sum = 0.f;
        float e[32];
#pragma unroll
        for (int d = 0; d < 32; d++) { e[d] = expf(S[tid][d] - m); sum += e[d]; }
        float inv = 1.0f / sum;
        float* ap = attn + (size_t)bh * CH * CH + tid * CH;
#pragma unroll
        for (int d = 0; d < 32; d++) ap[d] = e[d] * inv;
    }
}

// ---------------------------------------------------------------------------
// Apply attention: out[c,n] = sum_d attn[c,d] * v[d,n]  -> bf16 hi/lo
// ---------------------------------------------------------------------------
__global__ __launch_bounds__(256)
void attn_apply_kernel(const float* __restrict__ qkvdw,
                       const float* __restrict__ attn,
                       bf16* __restrict__ outh, bf16* __restrict__ outl)
{
    const int bh = blockIdx.y;
    const int b = bh >> 3, head = bh & 7;

    __shared__ float a[32][32];
    for (int i = threadIdx.x; i < 1024; i += 256)
        a[i >> 5][i & 31] = attn[(size_t)bh * 1024 + i];
    __syncthreads();

    const float2* vp2 = (const float2*)(qkvdw + ((size_t)(b * QKV_C + 2 * DIM + head * CH)) * HW);
    const size_t obase = ((size_t)(b * DIM + head * CH)) * HW;
    const int n2 = blockIdx.x * 256 + threadIdx.x;

    float2 o[32];
#pragma unroll
    for (int c = 0; c < 32; c++) { o[c].x = 0.f; o[c].y = 0.f; }
#pragma unroll
    for (int d = 0; d < 32; d++) {
        float2 vv = vp2[(size_t)d * (HW / 2) + n2];
#pragma unroll
        for (int c = 0; c < 32; c++) {
            o[c].x = fmaf(a[c][d], vv.x, o[c].x);
            o[c].y = fmaf(a[c][d], vv.y, o[c].y);
        }
    }
#pragma unroll
    for (int c = 0; c < 32; c++) {
        bf16 h0, l0, h1, l1;
        split2(o[c].x, h0, l0);
        split2(o[c].y, h1, l1);
        const size_t idx = obase + (size_t)c * HW + n2 * 2;
        *(uint32_t*)&outh[idx] = packbf(h0, h1);
        *(uint32_t*)&outl[idx] = packbf(l0, l1);
    }
}

// ---------------------------------------------------------------------------
extern "C" void kernel_launch(void* const* d_in, const int* in_sizes, int n_in,
                              void* d_out, int out_size)
{
    const float* x      = (const float*)d_in[0];
    const float* w_qkv  = (const float*)d_in[1];
    const float* w_dw   = (const float*)d_in[2];
    const float* temp   = (const float*)d_in[3];
    const float* w_proj = (const float*)d_in[4];
    const float* w_mlp1 = (const float*)d_in[5];
    const float* b_mlp1 = (const float*)d_in[6];
    const float* w_mlp2 = (const float*)d_in[7];
    const float* b_mlp2 = (const float*)d_in[8];
    float* out = (float*)d_out;

    bf16 *wqkvh, *wprjh, *w1h, *w2h;
    bf16 *aoh, *aol, *outh, *outl, *hidh, *hidl;
    float *b1p, *qkv, *qkvdw, *ssq, *part, *attn;
    cudaGetSymbolAddress((void**)&wqkvh, g_wqkvh);
    cudaGetSymbolAddress((void**)&wprjh, g_wprjh);
    cudaGetSymbolAddress((void**)&w1h,   g_w1h);
    cudaGetSymbolAddress((void**)&w2h,   g_w2h);
    cudaGetSymbolAddress((void**)&b1p,   g_b1p);
    cudaGetSymbolAddress((void**)&qkv,   g_qkv);
    cudaGetSymbolAddress((void**)&qkvdw, g_qkvdw);
    cudaGetSymbolAddress((void**)&ssq,   g_ssq);
    cudaGetSymbolAddress((void**)&part,  g_part);
    cudaGetSymbolAddress((void**)&attn,  g_attn);
    cudaGetSymbolAddress((void**)&aoh,   g_aoh);
    cudaGetSymbolAddress((void**)&aol,   g_aol);
    cudaGetSymbolAddress((void**)&outh,  g_outh);
    cudaGetSymbolAddress((void**)&outl,  g_outl);
    cudaGetSymbolAddress((void**)&hidh,  g_hidh);
    cudaGetSymbolAddress((void**)&hidl,  g_hidl);

    // 0) weight -> bf16 hi planes (3 micro-launches; launch #4 = qkv hgemm)
    prep_a_kernel<<<(PN1 + 255) / 256, 256>>>(w_qkv);
    prep_b_kernel<<<(PN2 + PN3 + 255) / 256, 256>>>(w_proj, w_mlp1);
    prep_c_kernel<<<(PN4 + PN5 + 255) / 256, 256>>>(w_mlp2, b_mlp1);

    // 1) qkv = bf16(w_qkv) @ x  (x split in-register during staging)
    hgemm_kernel<0, true><<<dim3(HW / 128, QKV_C / 128, BATCH), 256>>>(
        wqkvh, nullptr, nullptr, x, qkv, nullptr, nullptr, nullptr, nullptr,
        QKV_C, HW, DIM, DIM * HW, QKV_C);

    // 2) depthwise 3x3 (smem-tiled) + full-plane sumsq
    dwconv_kernel<<<dim3(BATCH * QKV_C), 256>>>(qkv, w_dw, qkvdw, ssq);

    // 3) partial logits (skewed, conflict-free, 8 splits)
    attn_partial_kernel<<<dim3(8, BATCH * HEADS), 256>>>(qkvdw, part);

    // 4) reduce + scale + softmax
    attn_softmax_kernel<<<dim3(BATCH * HEADS), 256>>>(part, ssq, temp, attn);

    // 5) apply attention -> bf16 hi/lo
    attn_apply_kernel<<<dim3(HW / 512, BATCH * HEADS), 256>>>(qkvdw, attn, aoh, aol);

    // 6) x1 = x + bf16(w_proj) @ attnout -> d_out fp32 + hi/lo
    hgemm_kernel<1, false><<<dim3(HW / 128, DIM / 128, BATCH), 256>>>(
        wprjh, aoh, aol, nullptr, out, outh, outl, nullptr, x,
        DIM, HW, DIM, DIM * HW, DIM);

    // 7) hidden = gelu(bf16(w1) @ x1 + b1) -> hi/lo
    hgemm_kernel<2, false><<<dim3(HW / 128, M1_PAD / 128, BATCH), 256>>>(
        w1h, outh, outl, nullptr, nullptr, hidh, hidl, b1p, nullptr,
        M1_PAD, HW, DIM, DIM * HW, M1_PAD);

    // 8) d_out = x1 + bf16(w2) @ hidden + b2  (in place)
    hgemm_kernel<3, false><<<dim3(HW / 128, DIM / 128, BATCH), 256>>>(
        w2h, hidh, hidl, nullptr, out, nullptr, nullptr, b_mlp2, out,
        DIM, HW, HID_PAD, M1_PAD * HW, DIM);
}

// round 16
// speedup vs baseline: 1.4471x; 1.2356x over previous
#include <cuda_runtime.h>
#include <cuda_bf16.h>
#include <cstdint>

// ---------------------------------------------------------------------------
#define BATCH   8
#define DIM     256
#define HEADS   8
#define CH      32
#define HW      4096
#define QKV_C   768
#define HIDDEN  307
#define HID_PAD 320
#define M1_PAD  384

typedef __nv_bfloat16 bf16;

// ---------------------------------------------------------------------------
// Scratch (static device globals). Pure-bf16 GEMM scheme: weights and
// activations single bf16 planes; accumulation in fp32.
// ---------------------------------------------------------------------------
__device__ bf16  g_wqkvh[QKV_C * DIM];
__device__ bf16  g_wprjh[DIM * DIM];
__device__ bf16  g_w1h  [M1_PAD * DIM];
__device__ bf16  g_w2h  [DIM * HID_PAD];
__device__ float g_b1p  [M1_PAD];
__device__ float g_qkv  [(size_t)BATCH * QKV_C * HW];
__device__ float g_qkvdw[(size_t)BATCH * QKV_C * HW];
__device__ float g_ssq  [BATCH * 2 * DIM];
__device__ float g_part [BATCH * HEADS * 8 * CH * CH];
__device__ float g_attn [BATCH * HEADS * CH * CH];
__device__ bf16  g_aoh  [(size_t)BATCH * DIM * HW];
__device__ bf16  g_outh [(size_t)BATCH * DIM * HW];
__device__ bf16  g_hidh [(size_t)BATCH * M1_PAD * HW];

// ---------------------------------------------------------------------------
__device__ __forceinline__ float gelu_tanh(float x) {
    float x3 = x * x * x;
    return 0.5f * x * (1.0f + tanhf(0.7978845608028654f * (x + 0.044715f * x3)));
}
__device__ __forceinline__ uint32_t packbf(bf16 a, bf16 b) {
    return ((uint32_t)__bfloat16_as_ushort(b) << 16) | (uint32_t)__bfloat16_as_ushort(a);
}
__device__ __forceinline__ void cvt_pack8(const float* f, uint32_t* hp) {
#pragma unroll
    for (int q = 0; q < 4; q++)
        hp[q] = packbf(__float2bfloat16(f[2 * q]), __float2bfloat16(f[2 * q + 1]));
}

// ---------------------------------------------------------------------------
// PTX wrappers
// ---------------------------------------------------------------------------
__device__ __forceinline__ void ldsm_x4(uint32_t& r0, uint32_t& r1, uint32_t& r2,
                                        uint32_t& r3, uint32_t addr) {
    asm volatile("ldmatrix.sync.aligned.m8n8.x4.shared.b16 {%0,%1,%2,%3}, [%4];"
                 : "=r"(r0), "=r"(r1), "=r"(r2), "=r"(r3) : "r"(addr));
}
__device__ __forceinline__ void ldsm_x4_t(uint32_t& r0, uint32_t& r1, uint32_t& r2,
                                          uint32_t& r3, uint32_t addr) {
    asm volatile("ldmatrix.sync.aligned.m8n8.x4.trans.shared.b16 {%0,%1,%2,%3}, [%4];"
                 : "=r"(r0), "=r"(r1), "=r"(r2), "=r"(r3) : "r"(addr));
}
__device__ __forceinline__ void mma16816(float* d, const uint32_t* a,
                                         uint32_t b0, uint32_t b1) {
    asm volatile(
        "mma.sync.aligned.m16n8k16.row.col.f32.bf16.bf16.f32 "
        "{%0,%1,%2,%3}, {%4,%5,%6,%7}, {%8,%9}, {%0,%1,%2,%3};"
        : "+f"(d[0]), "+f"(d[1]), "+f"(d[2]), "+f"(d[3])
        : "r"(a[0]), "r"(a[1]), "r"(a[2]), "r"(a[3]), "r"(b0), "r"(b1));
}

// ---------------------------------------------------------------------------
// prep (3 micro-kernels so the 4th launch = qkv hgemm, for ncu capture)
// ---------------------------------------------------------------------------
#define PN1 (QKV_C * DIM)
#define PN2 (DIM * DIM)
#define PN3 (M1_PAD * DIM)
#define PN4 (DIM * HID_PAD)
#define PN5 (M1_PAD)
__global__ void prep_a_kernel(const float* __restrict__ wqkv)
{
    int i = blockIdx.x * blockDim.x + threadIdx.x;
    if (i < PN1) g_wqkvh[i] = __float2bfloat16(wqkv[i]);
}
__global__ void prep_b_kernel(const float* __restrict__ wprj, const float* __restrict__ w1)
{
    int i = blockIdx.x * blockDim.x + threadIdx.x;
    if (i < PN2) { g_wprjh[i] = __float2bfloat16(wprj[i]); return; }
    i -= PN2;
    if (i < PN3) {
        int r = i >> 8;
        g_w1h[i] = __float2bfloat16((r < HIDDEN) ? w1[i] : 0.f);
    }
}
__global__ void prep_c_kernel(const float* __restrict__ w2, const float* __restrict__ b1)
{
    int i = blockIdx.x * blockDim.x + threadIdx.x;
    if (i < PN4) {
        int r = i / HID_PAD, c = i - r * HID_PAD;
        g_w2h[i] = __float2bfloat16((c < HIDDEN) ? w2[r * HIDDEN + c] : 0.f);
        return;
    }
    i -= PN4;
    if (i < PN5) g_b1p[i] = (i < HIDDEN) ? b1[i] : 0.f;
}

// ---------------------------------------------------------------------------
// Pure-bf16 tensor-core GEMM: C[b] = bf16(A)(MxK) @ bf16(B)[b](KxN) + epilogue.
// 16 MMAs per k-chunk, ALL on distinct accumulators (no intra-chunk RAW).
// If SPLITB: B is fp32, converted to bf16 in-register during staging.
//   EPI 0 (QKV):  Cf = acc
//   EPI 1 (PROJ): v = acc + Res; Cf = v; Ch = bf16(v)
//   EPI 2 (MLP1): v = gelu(acc + bias); Ch = bf16(v)
//   EPI 3 (MLP2): Cf = acc + bias + Res  (Res may alias Cf)
// ---------------------------------------------------------------------------
template <int EPI, bool SPLITB>
__global__ __launch_bounds__(256, 2)
void hgemm_kernel(const bf16* __restrict__ Ah,
                  const bf16* __restrict__ Bhg, const float* __restrict__ Bfg,
                  float* __restrict__ Cfg, bf16* __restrict__ Chg,
                  const float* __restrict__ bias, const float* __restrict__ Resg,
                  int M, int N, int K, int bStride, int mStrideC)
{
    const int batch = blockIdx.z;
    const size_t cOff = (size_t)batch * mStrideC * N;

    const int m0 = blockIdx.y * 128;
    const int n0 = blockIdx.x * 128;

    __shared__ __align__(16) bf16 sA[2][128][24];
    __shared__ __align__(16) bf16 sB[2][16][136];

    const int tid  = threadIdx.x;
    const int lane = tid & 31;
    const int warp = tid >> 5;
    const int wm = warp & 3;
    const int wn = warp >> 2;

    const uint32_t sA0 = (uint32_t)__cvta_generic_to_shared(&sA[0][0][0]);
    const uint32_t sB0 = (uint32_t)__cvta_generic_to_shared(&sB[0][0][0]);
    const uint32_t A_BUF = 128 * 24 * 2;
    const uint32_t B_BUF = 16 * 136 * 2;

    const uint32_t aAddr = sA0 + ((wm * 32 + (lane & 15)) * 24) * 2 + ((lane >> 4) * 16);
    const uint32_t bAddr = sB0 + ((lane & 15) * 136 + wn * 64 + (lane >> 4) * 8) * 2;

    const int am = tid >> 1, ahalf = tid & 1;
    const int bk = tid >> 4, bseg  = tid & 15;
    const bf16* gAh = Ah + (size_t)(m0 + am) * K + ahalf * 8;
    const bf16* gBh; const float* gBf;
    if (SPLITB) {
        gBf = Bfg + (size_t)batch * bStride + (size_t)bk * N + n0 + bseg * 8;
    } else {
        gBh = Bhg + (size_t)batch * bStride + (size_t)bk * N + n0 + bseg * 8;
    }

    const int numKT = K >> 4;
    int4 rah, rbh;
    float4 rf0, rf1;

    // preload chunk 0
    rah = *(const int4*)gAh;
    if (SPLITB) { rf0 = *(const float4*)gBf; rf1 = *((const float4*)gBf + 1); }
    else        { rbh = *(const int4*)gBh; }
    *(int4*)&sA[0][am][ahalf * 8] = rah;
    if (SPLITB) {
        float f[8] = {rf0.x, rf0.y, rf0.z, rf0.w, rf1.x, rf1.y, rf1.z, rf1.w};
        uint32_t hp[4];
        cvt_pack8(f, hp);
        *(int4*)&sB[0][bk][bseg * 8] = *(int4*)hp;
    } else {
        *(int4*)&sB[0][bk][bseg * 8] = rbh;
    }
    __syncthreads();

    float acc[2][8][4];
#pragma unroll
    for (int i = 0; i < 2; i++)
#pragma unroll
        for (int j = 0; j < 8; j++)
#pragma unroll
            for (int q = 0; q < 4; q++) acc[i][j][q] = 0.f;

#pragma unroll 2
    for (int kt = 0; kt < numKT; ++kt) {
        const int buf = kt & 1;
        if (kt + 1 < numKT) {
            const int kb = (kt + 1) << 4;
            rah = *(const int4*)(gAh + kb);
            if (SPLITB) {
                rf0 = *(const float4*)(gBf + (size_t)kb * N);
                rf1 = *((const float4*)(gBf + (size_t)kb * N) + 1);
            } else {
                rbh = *(const int4*)(gBh + (size_t)kb * N);
            }
        }

        uint32_t ah[2][4];
        {
            const uint32_t ab = aAddr + buf * A_BUF;
            ldsm_x4(ah[0][0], ah[0][1], ah[0][2], ah[0][3], ab);
            ldsm_x4(ah[1][0], ah[1][1], ah[1][2], ah[1][3], ab + 16 * 24 * 2);
        }
        const uint32_t bb = bAddr + buf * B_BUF;
        uint32_t bfr[8][2];
#pragma unroll
        for (int j2 = 0; j2 < 4; j2++)
            ldsm_x4_t(bfr[2 * j2][0], bfr[2 * j2][1],
                      bfr[2 * j2 + 1][0], bfr[2 * j2 + 1][1], bb + j2 * 32);

        // 16 MMAs, all distinct accumulators
#pragma unroll
        for (int j = 0; j < 8; j++) {
            mma16816(acc[0][j], ah[0], bfr[j][0], bfr[j][1]);
            mma16816(acc[1][j], ah[1], bfr[j][0], bfr[j][1]);
        }

        if (kt + 1 < numKT) {
            const int nb = buf ^ 1;
            *(int4*)&sA[nb][am][ahalf * 8] = rah;
            if (SPLITB) {
                float f[8] = {rf0.x, rf0.y, rf0.z, rf0.w, rf1.x, rf1.y, rf1.z, rf1.w};
                uint32_t hp[4];
                cvt_pack8(f, hp);
                *(int4*)&sB[nb][bk][bseg * 8] = *(int4*)hp;
            } else {
                *(int4*)&sB[nb][bk][bseg * 8] = rbh;
            }
        }
        __syncthreads();
    }

    // epilogue
    float* Cf = (EPI != 2) ? (Cfg + cOff) : nullptr;
    bf16*  Chp = (EPI == 1 || EPI == 2) ? (Chg + cOff) : nullptr;
    const float* R = (EPI == 1 || EPI == 3) ? (Resg + cOff) : nullptr;

    const int g = lane >> 2, t = lane & 3;
#pragma unroll
    for (int i = 0; i < 2; i++) {
#pragma unroll
        for (int half = 0; half < 2; half++) {
            const int r = m0 + wm * 32 + i * 16 + half * 8 + g;
            float bi = 0.f;
            if (EPI == 2 || EPI == 3) bi = bias[r];
#pragma unroll
            for (int j = 0; j < 8; j++) {
                const int c = n0 + wn * 64 + j * 8 + t * 2;
                float v0 = acc[i][j][half * 2 + 0];
                float v1 = acc[i][j][half * 2 + 1];
                const size_t idx = (size_t)r * N + c;
                if (EPI == 0) {
                    Cf[idx] = v0; Cf[idx + 1] = v1;
                } else if (EPI == 1) {
                    v0 += R[idx]; v1 += R[idx + 1];
                    Cf[idx] = v0; Cf[idx + 1] = v1;
                    *(uint32_t*)&Chp[idx] = packbf(__float2bfloat16(v0), __float2bfloat16(v1));
                } else if (EPI == 2) {
                    v0 = gelu_tanh(v0 + bi); v1 = gelu_tanh(v1 + bi);
                    *(uint32_t*)&Chp[idx] = packbf(__float2bfloat16(v0), __float2bfloat16(v1));
                } else {
                    v0 += bi + R[idx]; v1 += bi + R[idx + 1];
                    Cf[idx] = v0; Cf[idx + 1] = v1;
                }
            }
        }
    }
}

// ---------------------------------------------------------------------------
// Depthwise 3x3 conv, smem-tiled: one block per (b,ch) 64x64 plane.
// ---------------------------------------------------------------------------
__global__ __launch_bounds__(256)
void dwconv_kernel(const float* __restrict__ in, const float* __restrict__ w,
                   float* __restrict__ out, float* __restrict__ ssq)
{
    const int bc = blockIdx.x;
    const int b  = bc / QKV_C;
    const int ch = bc - b * QKV_C;
    const int tid = threadIdx.x;

    __shared__ float t[66][68];
    __shared__ float red[8];

    if (tid < 264) {
        if (tid < 68)       t[0][tid] = 0.f;
        else if (tid < 136) t[65][tid - 68] = 0.f;
        else if (tid < 200) t[tid - 136 + 1][0] = 0.f;
        else                t[tid - 200 + 1][65] = 0.f;
    }

    const float4* ip4 = (const float4*)(in + (size_t)bc * HW);
#pragma unroll
    for (int j = 0; j < 4; j++) {
        int idx = tid + j * 256;
        int h = idx >> 4, w4 = idx & 15;
        float4 v = ip4[idx];
        t[h + 1][w4 * 4 + 1] = v.x;
        t[h + 1][w4 * 4 + 2] = v.y;
        t[h + 1][w4 * 4 + 3] = v.z;
        t[h + 1][w4 * 4 + 4] = v.w;
    }

    const float* wp = w + ch * 9;
    float k0 = wp[0], k1 = wp[1], k2 = wp[2];
    float k3 = wp[3], k4 = wp[4], k5 = wp[5];
    float k6 = wp[6], k7 = wp[7], k8 = wp[8];
    __syncthreads();

    float4* op4 = (float4*)(out + (size_t)bc * HW);
    float ss = 0.f;

#pragma unroll
    for (int grp = 0; grp < 4; grp++) {
        const int n = grp * 1024 + tid * 4;
        const int h = n >> 6, w0 = n & 63;
        float s0 = 0.f, s1 = 0.f, s2 = 0.f, s3 = 0.f;
#pragma unroll
        for (int dh = 0; dh < 3; dh++) {
            const float* r = &t[h + dh][w0];
            float r0 = r[0], r1 = r[1], r2 = r[2], r3 = r[3], r4 = r[4], r5 = r[5];
            float ka = (dh == 0) ? k0 : (dh == 1) ? k3 : k6;
            float kb = (dh == 0) ? k1 : (dh == 1) ? k4 : k7;
            float kc = (dh == 0) ? k2 : (dh == 1) ? k5 : k8;
            s0 = fmaf(ka, r0, fmaf(kb, r1, fmaf(kc, r2, s0)));
            s1 = fmaf(ka, r1, fmaf(kb, r2, fmaf(kc, r3, s1)));
            s2 = fmaf(ka, r2, fmaf(kb, r3, fmaf(kc, r4, s2)));
            s3 = fmaf(ka, r3, fmaf(kb, r4, fmaf(kc, r5, s3)));
        }
        float4 o; o.x = s0; o.y = s1; o.z = s2; o.w = s3;
        op4[grp * 256 + tid] = o;
        ss += s0 * s0 + s1 * s1 + s2 * s2 + s3 * s3;
    }

    if (ch < 2 * DIM) {
#pragma unroll
        for (int o = 16; o; o >>= 1) ss += __shfl_down_sync(0xffffffffu, ss, o);
        if ((tid & 31) == 0) red[tid >> 5] = ss;
        __syncthreads();
        if (tid == 0) {
            float s = 0.f;
#pragma unroll
            for (int i = 0; i < 8; i++) s += red[i];
            ssq[b * 2 * DIM + ch] = s;
        }
    }
}

// ---------------------------------------------------------------------------
// Partial attention logits, skewed smem (conflict-free LDS.128), 8 splits.
// ---------------------------------------------------------------------------
#define QP 160
__global__ __launch_bounds__(256)
void attn_partial_kernel(const float* __restrict__ qkvdw, float* __restrict__ part)
{
    const int split = blockIdx.x;
    const int bh = blockIdx.y;
    const int b = bh >> 3, head = bh & 7;

    const float* qp = qkvdw + ((size_t)(b * QKV_C + head * CH)) * HW;
    const float* kp = qkvdw + ((size_t)(b * QKV_C + DIM + head * CH)) * HW;

    __shared__ __align__(16) float qs[32][QP];
    __shared__ __align__(16) float ks[32][QP];

    const int tid = threadIdx.x;
    const int slice = tid >> 6;
    const int t64 = tid & 63;
    const int c0 = (t64 & 7) * 4;
    const int d0 = (t64 >> 3) * 4;
    const int skq = (c0 >> 2) * 4;
    const int skk = (d0 >> 2) * 4;

    float acc[4][4];
#pragma unroll
    for (int i = 0; i < 4; i++)
#pragma unroll
        for (int q = 0; q < 4; q++) acc[i][q] = 0.f;

    for (int t = 0; t < 4; ++t) {
        const int n0 = split * 512 + t * 128;
        __syncthreads();
#pragma unroll
        for (int it = 0; it < 4; it++) {
            int idx = tid + it * 256;
            int row = idx >> 5, j4 = idx & 31;
            int sk = (row >> 2) * 4;
            *(float4*)&qs[row][j4 * 4 + sk] = *(const float4*)&qp[(size_t)row * HW + n0 + j4 * 4];
            *(float4*)&ks[row][j4 * 4 + sk] = *(const float4*)&kp[(size_t)row * HW + n0 + j4 * 4];
        }
        __syncthreads();
#pragma unroll
        for (int jj = 0; jj < 32; jj += 4) {
            const int j = slice * 32 + jj;
            float4 qv[4], kv[4];
#pragma unroll
            for (int i = 0; i < 4; i++) qv[i] = *(const float4*)&qs[c0 + i][j + skq];
#pragma unroll
            for (int q = 0; q < 4; q++) kv[q] = *(const float4*)&ks[d0 + q][j + skk];
#pragma unroll
            for (int i = 0; i < 4; i++)
#pragma unroll
                for (int q = 0; q < 4; q++) {
                    acc[i][q] = fmaf(qv[i].x, kv[q].x, acc[i][q]);
                    acc[i][q] = fmaf(qv[i].y, kv[q].y, acc[i][q]);
                    acc[i][q] = fmaf(qv[i].z, kv[q].z, acc[i][q]);
                    acc[i][q] = fmaf(qv[i].w, kv[q].w, acc[i][q]);
                }
        }
    }

    __syncthreads();
    float* red = &qs[0][0];
#pragma unroll
    for (int i = 0; i < 4; i++)
#pragma unroll
        for (int q = 0; q < 4; q++)
            red[(slice * 64 + t64) * 16 + i * 4 + q] = acc[i][q];
    __syncthreads();

    float* pp = part + ((size_t)(bh * 8 + split)) * (CH * CH);
#pragma unroll
    for (int qq = 0; qq < 4; qq++) {
        const int e = tid * 4 + qq;
        const int c = e >> 5, d = e & 31;
        const int t2 = (d >> 2) * 8 + (c >> 2);
        const int f = (c & 3) * 4 + (d & 3);
        pp[e] = red[(0 * 64 + t2) * 16 + f] + red[(1 * 64 + t2) * 16 + f]
              + red[(2 * 64 + t2) * 16 + f] + red[(3 * 64 + t2) * 16 + f];
    }
}

// ---------------------------------------------------------------------------
// Reduce partials, fold norms + temperature, softmax.
// ---------------------------------------------------------------------------
__global__ __launch_bounds__(256)
void attn_softmax_kernel(const float* __restrict__ part,
                         const float* __restrict__ ssq,
                         const float* __restrict__ temp,
                         float* __restrict__ attn)
{
    const int bh = blockIdx.x;
    const int b = bh >> 3, head = bh & 7;
    const int tid = threadIdx.x;

    __shared__ float S[32][33];
    __shared__ float fq[32], fk[32];

    if (tid < 64) {
        int isK = tid >> 5, c = tid & 31;
        int ch = isK ? (DIM + head * CH + c) : (head * CH + c);
        float s = ssq[b * 2 * DIM + ch];
        float f = 1.0f / fmaxf(sqrtf(s), 1e-12f);
        if (isK) fk[c] = f; else fq[c] = f;
    }
    __syncthreads();

    const float T = temp[head];
#pragma unroll
    for (int r = 0; r < 4; r++) {
        int e = tid + r * 256;
        int c = e >> 5, d = e & 31;
        float s = 0.f;
#pragma unroll
        for (int p = 0; p < 8; p++) s += part[((size_t)(bh * 8 + p)) * (CH * CH) + e];
        S[c][d] = s * fq[c] * fk[d] * T;
    }
    __syncthreads();

    if (tid < 32) {
        float m = -1e30f;
#pragma unroll
        for (int d = 0; d < 32; d++) m = fmaxf(m, S[tid][d]);
        float sum = 0.f;
        float e[32];
#pragma unroll
        for (int d = 0; d < 32; d++) { e[d] = expf(S[tid][d] - m); sum += e[d]; }
        float inv = 1.0f / sum;
        float* ap = attn + (size_t)bh * CH * CH + tid * CH;
#pragma unroll
        for (int d = 0; d < 32; d++) ap[d] = e[d] * inv;
    }
}

// ---------------------------------------------------------------------------
// Apply attention: out[c,n] = sum_d attn[c,d] * v[d,n]  -> bf16 (single plane)
// ---------------------------------------------------------------------------
__global__ __launch_bounds__(256)
void attn_apply_kernel(const float* __restrict__ qkvdw,
                       const float* __restrict__ attn,
                       bf16* __restrict__ outh)
{
    const int bh = blockIdx.y;
    const int b = bh >> 3, head = bh & 7;

    __shared__ float a[32][32];
    for (int i = threadIdx.x; i < 1024; i += 256)
        a[i >> 5][i & 31] = attn[(size_t)bh * 1024 + i];
    __syncthreads();

    const float2* vp2 = (const float2*)(qkvdw + ((size_t)(b * QKV_C + 2 * DIM + head * CH)) * HW);
    const size_t obase = ((size_t)(b * DIM + head * CH)) * HW;
    const int n2 = blockIdx.x * 256 + threadIdx.x;

    float2 o[32];
#pragma unroll
    for (int c = 0; c < 32; c++) { o[c].x = 0.f; o[c].y = 0.f; }
#pragma unroll
    for (int d = 0; d < 32; d++) {
        float2 vv = vp2[(size_t)d * (HW / 2) + n2];
#pragma unroll
        for (int c = 0; c < 32; c++) {
            o[c].x = fmaf(a[c][d], vv.x, o[c].x);
            o[c].y = fmaf(a[c][d], vv.y, o[c].y);
        }
    }
#pragma unroll
    for (int c = 0; c < 32; c++) {
        const size_t idx = obase + (size_t)c * HW + n2 * 2;
        *(uint32_t*)&outh[idx] =
            packbf(__float2bfloat16(o[c].x), __float2bfloat16(o[c].y));
    }
}

// ---------------------------------------------------------------------------
extern "C" void kernel_launch(void* const* d_in, const int* in_sizes, int n_in,
                              void* d_out, int out_size)
{
    const float* x      = (const float*)d_in[0];
    const float* w_qkv  = (const float*)d_in[1];
    const float* w_dw   = (const float*)d_in[2];
    const float* temp   = (const float*)d_in[3];
    const float* w_proj = (const float*)d_in[4];
    const float* w_mlp1 = (const float*)d_in[5];
    const float* b_mlp1 = (const float*)d_in[6];
    const float* w_mlp2 = (const float*)d_in[7];
    const float* b_mlp2 = (const float*)d_in[8];
    float* out = (float*)d_out;

    bf16 *wqkvh, *wprjh, *w1h, *w2h, *aoh, *outh, *hidh;
    float *b1p, *qkv, *qkvdw, *ssq, *part, *attn;
    cudaGetSymbolAddress((void**)&wqkvh, g_wqkvh);
    cudaGetSymbolAddress((void**)&wprjh, g_wprjh);
    cudaGetSymbolAddress((void**)&w1h,   g_w1h);
    cudaGetSymbolAddress((void**)&w2h,   g_w2h);
    cudaGetSymbolAddress((void**)&b1p,   g_b1p);
    cudaGetSymbolAddress((void**)&qkv,   g_qkv);
    cudaGetSymbolAddress((void**)&qkvdw, g_qkvdw);
    cudaGetSymbolAddress((void**)&ssq,   g_ssq);
    cudaGetSymbolAddress((void**)&part,  g_part);
    cudaGetSymbolAddress((void**)&attn,  g_attn);
    cudaGetSymbolAddress((void**)&aoh,   g_aoh);
    cudaGetSymbolAddress((void**)&outh,  g_outh);
    cudaGetSymbolAddress((void**)&hidh,  g_hidh);

    // 0) weight -> bf16 planes (3 micro-launches; launch #4 = qkv hgemm)
    prep_a_kernel<<<(PN1 + 255) / 256, 256>>>(w_qkv);
    prep_b_kernel<<<(PN2 + PN3 + 255) / 256, 256>>>(w_proj, w_mlp1);
    prep_c_kernel<<<(PN4 + PN5 + 255) / 256, 256>>>(w_mlp2, b_mlp1);

    // 1) qkv = bf16(w_qkv) @ bf16(x)  (x converted in-register during staging)
    hgemm_kernel<0, true><<<dim3(HW / 128, QKV_C / 128, BATCH), 256>>>(
        wqkvh, nullptr, x, qkv, nullptr, nullptr, nullptr,
        QKV_C, HW, DIM, DIM * HW, QKV_C);

    // 2) depthwise 3x3 (smem-tiled) + full-plane sumsq
    dwconv_kernel<<<dim3(BATCH * QKV_C), 256>>>(qkv, w_dw, qkvdw, ssq);

    // 3) partial logits (skewed, conflict-free, 8 splits)
    attn_partial_kernel<<<dim3(8, BATCH * HEADS), 256>>>(qkvdw, part);

    // 4) reduce + scale + softmax
    attn_softmax_kernel<<<dim3(BATCH * HEADS), 256>>>(part, ssq, temp, attn);

    // 5) apply attention -> bf16
    attn_apply_kernel<<<dim3(HW / 512, BATCH * HEADS), 256>>>(qkvdw, attn, aoh);

    // 6) x1 = x + bf16(w_proj) @ ao -> d_out fp32 + bf16
    hgemm_kernel<1, false><<<dim3(HW / 128, DIM / 128, BATCH), 256>>>(
        wprjh, aoh, nullptr, out, outh, nullptr, x,
        DIM, HW, DIM, DIM * HW, DIM);

    // 7) hidden = gelu(bf16(w1) @ x1 + b1) -> bf16
    hgemm_kernel<2, false><<<dim3(HW / 128, M1_PAD / 128, BATCH), 256>>>(
        w1h, outh, nullptr, nullptr, hidh, b1p, nullptr,
        M1_PAD, HW, DIM, DIM * HW, M1_PAD);

    // 8) d_out = x1 + bf16(w2) @ hidden + b2  (in place)
    hgemm_kernel<3, false><<<dim3(HW / 128, DIM / 128, BATCH), 256>>>(
        w2h, hidh, nullptr, out, nullptr, b_mlp2, out,
        DIM, HW, HID_PAD, M1_PAD * HW, DIM);
}